// round 4
// baseline (speedup 1.0000x reference)
#include <cuda_runtime.h>

#define NCTA 128
#define TPB  256

// Persistent global state (statically zero-initialized; barrier state returns
// to a consistent value after every launch, so graph replays are fine).
__device__ float g_h0[2 * 128 * 256];
__device__ float g_h1[2 * 128 * 256];
__device__ unsigned g_cnt = 0;
__device__ unsigned g_gen = 0;

typedef unsigned long long u64;

__device__ __forceinline__ void fma2(u64 &d, u64 a, u64 b) {
    asm("fma.rn.f32x2 %0, %1, %2, %0;" : "+l"(d) : "l"(a), "l"(b));
}
__device__ __forceinline__ float hsum(u64 a) {
    union { u64 u; float2 f; } x; x.u = a; return x.f.x + x.f.y;
}
__device__ __forceinline__ float sigm(float x) {
    return __fdividef(1.f, 1.f + __expf(-x));
}

__device__ __forceinline__ void gridbar() {
    __syncthreads();
    if (threadIdx.x == 0) {
        unsigned g = *(volatile unsigned *)&g_gen;
        __threadfence();
        if (atomicAdd(&g_cnt, 1u) == NCTA - 1) {
            g_cnt = 0;
            __threadfence();
            atomicAdd(&g_gen, 1u);
        } else {
            while (*(volatile unsigned *)&g_gen == g) { __nanosleep(32); }
        }
    }
    __syncthreads();
}

extern __shared__ float sm[];

__global__ __launch_bounds__(TPB, 1)
void regime_kernel(const float *__restrict__ X,    const float *__restrict__ vix,
                   const float *__restrict__ Wih0, const float *__restrict__ Whh0,
                   const float *__restrict__ bih0, const float *__restrict__ bhh0,
                   const float *__restrict__ Wih1, const float *__restrict__ Whh1,
                   const float *__restrict__ bih1, const float *__restrict__ bhh1,
                   const float *__restrict__ lng,  const float *__restrict__ lnb,
                   const float *__restrict__ lw,   const float *__restrict__ lb,
                   const float *__restrict__ rbud, float *__restrict__ out)
{
    float *W0  = sm;                 // 64 rows x 256, swizzled
    float *W1i = sm + 16384;
    float *W1h = sm + 32768;
    float *h0t = sm + 49152;         // 16 x 256
    float *h1t = sm + 53248;         // 16 x 256
    float *xt  = sm + 57344;         // 16 x 16

    const int t    = threadIdx.x;
    const int bid  = blockIdx.x;
    const int hg   = bid & 15;       // hidden group (16 cols)
    const int bg   = bid >> 4;       // batch group (16 rows)
    const int jg   = t & 63;         // (j,gate): jg = 4*j + g
    const int bh   = t >> 6;         // batch quad id (4 batches each)
    const int g    = jg & 3;
    const int j    = jg >> 2;
    const int rot  = jg & 7;
    const int lane = t & 31;
    const int base = lane & ~3;
    const int R    = g * 256 + hg * 16 + j;   // global gate-row

    // ---- load CTA weight slices into smem, XOR-16B swizzled by row ----
    for (int idx = t; idx < 4096; idx += TPB) {
        int rjg = idx >> 6, q = idx & 63;
        int rr = (rjg & 3) * 256 + hg * 16 + (rjg >> 2);
        int ds = rjg * 256 + ((q ^ (rjg & 7)) << 2);
        *(float4 *)(W0  + ds) = __ldg((const float4 *)(Whh0 + rr * 256 + q * 4));
        *(float4 *)(W1i + ds) = __ldg((const float4 *)(Wih1 + rr * 256 + q * 4));
        *(float4 *)(W1h + ds) = __ldg((const float4 *)(Whh1 + rr * 256 + q * 4));
    }
    // per-thread input weights + fused biases
    float wx[16];
#pragma unroll
    for (int i = 0; i < 16; i += 4) {
        float4 v = __ldg((const float4 *)(Wih0 + R * 16 + i));
        wx[i] = v.x; wx[i + 1] = v.y; wx[i + 2] = v.z; wx[i + 3] = v.w;
    }
    const float b0 = bih0[R] + bhh0[R];
    const float b1 = bih1[R] + bhh1[R];

    float c0[4] = {0, 0, 0, 0}, c1[4] = {0, 0, 0, 0};

    const ulonglong2 *w0p = (const ulonglong2 *)(W0  + jg * 256);
    const ulonglong2 *wip = (const ulonglong2 *)(W1i + jg * 256);
    const ulonglong2 *whp = (const ulonglong2 *)(W1h + jg * 256);
    const ulonglong2 *h0r0 = (const ulonglong2 *)(h0t + (bh * 4 + 0) * 256);
    const ulonglong2 *h0r1 = (const ulonglong2 *)(h0t + (bh * 4 + 1) * 256);
    const ulonglong2 *h0r2 = (const ulonglong2 *)(h0t + (bh * 4 + 2) * 256);
    const ulonglong2 *h0r3 = (const ulonglong2 *)(h0t + (bh * 4 + 3) * 256);
    const ulonglong2 *h1r0 = (const ulonglong2 *)(h1t + (bh * 4 + 0) * 256);
    const ulonglong2 *h1r1 = (const ulonglong2 *)(h1t + (bh * 4 + 1) * 256);
    const ulonglong2 *h1r2 = (const ulonglong2 *)(h1t + (bh * 4 + 2) * 256);
    const ulonglong2 *h1r3 = (const ulonglong2 *)(h1t + (bh * 4 + 3) * 256);

    // ---- main pipelined recurrence: iter k does layer0 step k + layer1 step k-1 ----
    for (int k = 0; k <= 1024; k++) {
        const int pp = (k - 1) & 1;                    // read parity
        if (k == 0) {
            for (int f4 = t; f4 < 1024; f4 += TPB)
                ((float4 *)h0t)[f4] = make_float4(0, 0, 0, 0);
        } else {
            const float4 *src = (const float4 *)(g_h0 + pp * 32768 + bg * 4096);
            for (int f4 = t; f4 < 1024; f4 += TPB)
                ((float4 *)h0t)[f4] = __ldcg(src + f4);
        }
        if (k <= 1) {
            for (int f4 = t; f4 < 1024; f4 += TPB)
                ((float4 *)h1t)[f4] = make_float4(0, 0, 0, 0);
        } else {
            const float4 *src = (const float4 *)(g_h1 + pp * 32768 + bg * 4096);
            for (int f4 = t; f4 < 1024; f4 += TPB)
                ((float4 *)h1t)[f4] = __ldcg(src + f4);
        }
        if (k < 1024 && t < 64) {
            int bl = t >> 2, i4 = t & 3;
            ((float4 *)xt)[t] =
                __ldg((const float4 *)(X + ((bg * 16 + bl) * 1024 + k) * 16 + i4 * 4));
        }
        __syncthreads();

        u64 a0[4] = {0, 0, 0, 0}, aA[4] = {0, 0, 0, 0}, aB[4] = {0, 0, 0, 0};
#pragma unroll 8
        for (int q = 0; q < 64; q++) {
            const int pq = q ^ rot;
            ulonglong2 w0 = w0p[pq];
            ulonglong2 wi = wip[pq];
            ulonglong2 wh = whp[pq];
            ulonglong2 h, z;
            h = h0r0[q]; z = h1r0[q];
            fma2(a0[0], w0.x, h.x); fma2(a0[0], w0.y, h.y);
            fma2(aA[0], wi.x, h.x); fma2(aA[0], wi.y, h.y);
            fma2(aB[0], wh.x, z.x); fma2(aB[0], wh.y, z.y);
            h = h0r1[q]; z = h1r1[q];
            fma2(a0[1], w0.x, h.x); fma2(a0[1], w0.y, h.y);
            fma2(aA[1], wi.x, h.x); fma2(aA[1], wi.y, h.y);
            fma2(aB[1], wh.x, z.x); fma2(aB[1], wh.y, z.y);
            h = h0r2[q]; z = h1r2[q];
            fma2(a0[2], w0.x, h.x); fma2(a0[2], w0.y, h.y);
            fma2(aA[2], wi.x, h.x); fma2(aA[2], wi.y, h.y);
            fma2(aB[2], wh.x, z.x); fma2(aB[2], wh.y, z.y);
            h = h0r3[q]; z = h1r3[q];
            fma2(a0[3], w0.x, h.x); fma2(a0[3], w0.y, h.y);
            fma2(aA[3], wi.x, h.x); fma2(aA[3], wi.y, h.y);
            fma2(aB[3], wh.x, z.x); fma2(aB[3], wh.y, z.y);
        }

        if (k < 1024) {                      // layer-0 step k
#pragma unroll
            for (int bi = 0; bi < 4; bi++) {
                const float4 *xr = (const float4 *)(xt + (bh * 4 + bi) * 16);
                float xc = 0.f;
#pragma unroll
                for (int i4 = 0; i4 < 4; i4++) {
                    float4 xv = xr[i4];
                    xc += wx[i4 * 4 + 0] * xv.x + wx[i4 * 4 + 1] * xv.y +
                          wx[i4 * 4 + 2] * xv.z + wx[i4 * 4 + 3] * xv.w;
                }
                float v = hsum(a0[bi]) + b0 + xc;
                v = (g == 2) ? tanhf(v) : sigm(v);
                float iv = __shfl_sync(0xffffffffu, v, base);
                float fv = __shfl_sync(0xffffffffu, v, base + 1);
                float gv = __shfl_sync(0xffffffffu, v, base + 2);
                float ov = __shfl_sync(0xffffffffu, v, base + 3);
                if (g == 0) {
                    c0[bi] = fv * c0[bi] + iv * gv;
                    float hh = ov * tanhf(c0[bi]);
                    __stcg(g_h0 + (k & 1) * 32768 +
                           (bg * 16 + bh * 4 + bi) * 256 + hg * 16 + j, hh);
                }
            }
        }
        if (k >= 1) {                        // layer-1 step k-1
#pragma unroll
            for (int bi = 0; bi < 4; bi++) {
                float v = hsum(aA[bi]) + hsum(aB[bi]) + b1;
                v = (g == 2) ? tanhf(v) : sigm(v);
                float iv = __shfl_sync(0xffffffffu, v, base);
                float fv = __shfl_sync(0xffffffffu, v, base + 1);
                float gv = __shfl_sync(0xffffffffu, v, base + 2);
                float ov = __shfl_sync(0xffffffffu, v, base + 3);
                if (g == 0) {
                    c1[bi] = fv * c1[bi] + iv * gv;
                    float hh = ov * tanhf(c1[bi]);
                    __stcg(g_h1 + (k & 1) * 32768 +
                           (bg * 16 + bh * 4 + bi) * 256 + hg * 16 + j, hh);
                }
            }
        }
        __threadfence();
        gridbar();
    }

    // ---- head: CTA 0, one thread per batch. h_last = layer1 state after step 1023,
    //      which iter k=1024 wrote to parity (1024&1)=0 of g_h1. ----
    if (bid == 0 && t < 128) {
        const int b = t;
        const float *h = g_h1 + b * 256;
        float s = 0.f, s2 = 0.f;
        for (int i = 0; i < 256; i++) { float v = __ldcg(h + i); s += v; s2 += v * v; }
        float mu  = s * (1.f / 256.f);
        float var = s2 * (1.f / 256.f) - mu * mu;
        float inv = rsqrtf(var + 1e-5f);
        float l0 = lb[0], l1 = lb[1], l2 = lb[2];
        for (int i = 0; i < 256; i++) {
            float v  = __ldcg(h + i);
            float hn = (v - mu) * inv * lng[i] + lnb[i];
            l0 += hn * lw[i]; l1 += hn * lw[256 + i]; l2 += hn * lw[512 + i];
        }
        float m  = fmaxf(l0, fmaxf(l1, l2));
        float e0 = __expf(l0 - m), e1 = __expf(l1 - m), e2 = __expf(l2 - m);
        float es = e0 + e1 + e2;
        float p0 = e0 / es, p1 = e1 / es, p2 = e2 / es;

        float bm[3], bs[3];
#pragma unroll
        for (int r = 0; r < 3; r++) {
            float mm = -1e30f;
            for (int p = 0; p < 32; p++) mm = fmaxf(mm, rbud[r * 32 + p]);
            float ss = 0.f;
            for (int p = 0; p < 32; p++) ss += __expf(rbud[r * 32 + p] - mm);
            bm[r] = mm; bs[r] = ss;
        }
        float w0s = p0 / bs[0], w1s = p1 / bs[1], w2s = p2 / bs[2];
        float bb[32];
        float eqs = 0.f, dfs = 0.f;
        for (int p = 0; p < 32; p++) {
            float v = w0s * __expf(rbud[p]      - bm[0]) +
                      w1s * __expf(rbud[32 + p] - bm[1]) +
                      w2s * __expf(rbud[64 + p] - bm[2]);
            bb[p] = v;
            if (p < 24) eqs += v; else dfs += v;
        }
        bool  mask      = vix[b] >= 30.0f;
        float shortfall = 0.4f - dfs;
        float ratio     = fminf(shortfall / fmaxf(eqs, 1e-8f), 0.8f);
        bool  apply     = mask && (shortfall > 0.f) && (eqs > 1e-8f);
        float bsel[32], bsum = 0.f;
        for (int p = 0; p < 32; p++) {
            float b2 = (p < 24) ? bb[p] * (1.f - ratio) : bb[p] + shortfall * (1.f / 8.f);
            float v  = apply ? b2 : bb[p];
            bsel[p] = v; bsum += v;
        }
        float innorm = 1.f / (bsum + 1e-8f);
        for (int p = 0; p < 32; p++)
            out[b * 32 + p] = mask ? bsel[p] * innorm : bb[p];
        out[4096 + b * 3 + 0] = p0;
        out[4096 + b * 3 + 1] = p1;
        out[4096 + b * 3 + 2] = p2;
    }
}

extern "C" void kernel_launch(void *const *d_in, const int *in_sizes, int n_in,
                              void *d_out, int out_size)
{
    (void)in_sizes; (void)n_in; (void)out_size;
    static int smem_set = 0;
    const int smem = 57600 * 4;   // 230400 B
    if (!smem_set) {
        cudaFuncSetAttribute(regime_kernel,
                             cudaFuncAttributeMaxDynamicSharedMemorySize, smem);
        smem_set = 1;
    }
    regime_kernel<<<NCTA, TPB, smem>>>(
        (const float *)d_in[0],  (const float *)d_in[1],  (const float *)d_in[2],
        (const float *)d_in[3],  (const float *)d_in[4],  (const float *)d_in[5],
        (const float *)d_in[6],  (const float *)d_in[7],  (const float *)d_in[8],
        (const float *)d_in[9],  (const float *)d_in[10], (const float *)d_in[11],
        (const float *)d_in[12], (const float *)d_in[13], (const float *)d_in[14],
        (float *)d_out);
}

// round 6
// speedup vs baseline: 1.0388x; 1.0388x over previous
#include <cuda_runtime.h>

#define NCTA 128
#define TPB  512

// Persistent global state (statically zero-initialized; barrier state returns
// to a consistent value after every launch, so graph replays are fine).
__device__ float g_h0[2 * 128 * 256];
__device__ float g_h1[2 * 128 * 256];
__device__ unsigned g_cnt = 0;
__device__ unsigned g_gen = 0;

typedef unsigned long long u64;

__device__ __forceinline__ void fma2(u64 &d, u64 a, u64 b) {
    asm("fma.rn.f32x2 %0, %1, %2, %0;" : "+l"(d) : "l"(a), "l"(b));
}
__device__ __forceinline__ void add2(u64 &d, u64 a) {
    asm("add.rn.f32x2 %0, %0, %1;" : "+l"(d) : "l"(a));
}
__device__ __forceinline__ float hsum(u64 a) {
    union { u64 u; float2 f; } x; x.u = a; return x.f.x + x.f.y;
}
__device__ __forceinline__ float sigm(float x) {
    return __fdividef(1.f, 1.f + __expf(-x));
}

__device__ __forceinline__ void gridbar() {
    __syncthreads();
    if (threadIdx.x == 0) {
        unsigned g = *(volatile unsigned *)&g_gen;
        __threadfence();
        if (atomicAdd(&g_cnt, 1u) == NCTA - 1) {
            g_cnt = 0;
            __threadfence();
            atomicAdd(&g_gen, 1u);
        } else {
            while (*(volatile unsigned *)&g_gen == g) { __nanosleep(32); }
        }
    }
    __syncthreads();
}

extern __shared__ float sm[];

__global__ __launch_bounds__(TPB, 1)
void regime_kernel(const float *__restrict__ X,    const float *__restrict__ vix,
                   const float *__restrict__ Wih0, const float *__restrict__ Whh0,
                   const float *__restrict__ bih0, const float *__restrict__ bhh0,
                   const float *__restrict__ Wih1, const float *__restrict__ Whh1,
                   const float *__restrict__ bih1, const float *__restrict__ bhh1,
                   const float *__restrict__ lng,  const float *__restrict__ lnb,
                   const float *__restrict__ lw,   const float *__restrict__ lb,
                   const float *__restrict__ rbud, float *__restrict__ out)
{
    float *W0  = sm;                 // 64 rows x 256, swizzled
    float *W1i = sm + 16384;
    float *W1h = sm + 32768;
    float *h0t = sm + 49152;         // 16 x 256
    float *h1t = sm + 53248;         // 16 x 256
    float *xt  = sm + 57344;         // 16 x 16

    const int t    = threadIdx.x;
    const int bid  = blockIdx.x;
    const int hg   = bid & 15;        // hidden group (16 cols)
    const int bg   = bid >> 4;        // batch group (16 rows)
    const int jg   = t & 63;          // (j,gate): jg = 4*j + g
    const int bh   = (t >> 6) & 3;    // batch quad id (4 batches each)
    const int kh   = t >> 8;          // K-half (0: q<32, 1: q>=32)
    const int g    = jg & 3;
    const int j    = jg >> 2;
    const int rot  = jg & 7;
    const int lane = t & 31;
    const int base = lane & ~3;
    const int R    = g * 256 + hg * 16 + j;   // global gate-row

    // ---- load CTA weight slices into smem, XOR-16B swizzled by row ----
    for (int idx = t; idx < 4096; idx += TPB) {
        int rjg = idx >> 6, q = idx & 63;
        int rr = (rjg & 3) * 256 + hg * 16 + (rjg >> 2);
        int ds = rjg * 256 + ((q ^ (rjg & 7)) << 2);
        *(float4 *)(W0  + ds) = __ldg((const float4 *)(Whh0 + rr * 256 + q * 4));
        *(float4 *)(W1i + ds) = __ldg((const float4 *)(Wih1 + rr * 256 + q * 4));
        *(float4 *)(W1h + ds) = __ldg((const float4 *)(Whh1 + rr * 256 + q * 4));
    }
    // per-thread input weights (this K-half's 8 of 16) + fused biases
    float wx[8];
#pragma unroll
    for (int i = 0; i < 8; i += 4) {
        float4 v = __ldg((const float4 *)(Wih0 + R * 16 + kh * 8 + i));
        wx[i] = v.x; wx[i + 1] = v.y; wx[i + 2] = v.z; wx[i + 3] = v.w;
    }
    const float b0 = bih0[R] + bhh0[R];
    const float b1 = bih1[R] + bhh1[R];

    float c0[4] = {0, 0, 0, 0}, c1[4] = {0, 0, 0, 0};

    const int q0 = kh << 5;
    const ulonglong2 *w0p = (const ulonglong2 *)(W0  + jg * 256);
    const ulonglong2 *wip = (const ulonglong2 *)(W1i + jg * 256);
    const ulonglong2 *whp = (const ulonglong2 *)(W1h + jg * 256);
    const ulonglong2 *h0r0 = (const ulonglong2 *)(h0t + (bh * 4 + 0) * 256);
    const ulonglong2 *h0r1 = (const ulonglong2 *)(h0t + (bh * 4 + 1) * 256);
    const ulonglong2 *h0r2 = (const ulonglong2 *)(h0t + (bh * 4 + 2) * 256);
    const ulonglong2 *h0r3 = (const ulonglong2 *)(h0t + (bh * 4 + 3) * 256);
    const ulonglong2 *h1r0 = (const ulonglong2 *)(h1t + (bh * 4 + 0) * 256);
    const ulonglong2 *h1r1 = (const ulonglong2 *)(h1t + (bh * 4 + 1) * 256);
    const ulonglong2 *h1r2 = (const ulonglong2 *)(h1t + (bh * 4 + 2) * 256);
    const ulonglong2 *h1r3 = (const ulonglong2 *)(h1t + (bh * 4 + 3) * 256);

    // ---- main pipelined recurrence: iter k does layer0 step k + layer1 step k-1 ----
    for (int k = 0; k <= 1024; k++) {
        const int pp = (k - 1) & 1;                    // read parity
        if (k == 0) {
            for (int f4 = t; f4 < 1024; f4 += TPB)
                ((float4 *)h0t)[f4] = make_float4(0, 0, 0, 0);
        } else {
            const float4 *src = (const float4 *)(g_h0 + pp * 32768 + bg * 4096);
            for (int f4 = t; f4 < 1024; f4 += TPB)
                ((float4 *)h0t)[f4] = __ldcg(src + f4);
        }
        if (k <= 1) {
            for (int f4 = t; f4 < 1024; f4 += TPB)
                ((float4 *)h1t)[f4] = make_float4(0, 0, 0, 0);
        } else {
            const float4 *src = (const float4 *)(g_h1 + pp * 32768 + bg * 4096);
            for (int f4 = t; f4 < 1024; f4 += TPB)
                ((float4 *)h1t)[f4] = __ldcg(src + f4);
        }
        if (k < 1024 && t < 64) {
            int bl = t >> 2, i4 = t & 3;
            ((float4 *)xt)[t] =
                __ldg((const float4 *)(X + ((bg * 16 + bl) * 1024 + k) * 16 + i4 * 4));
        }
        __syncthreads();

        u64 a0[4] = {0, 0, 0, 0}, aA[4] = {0, 0, 0, 0}, aB[4] = {0, 0, 0, 0};
#pragma unroll 4
        for (int qq = 0; qq < 32; qq++) {
            const int q  = q0 + qq;
            const int pq = q ^ rot;
            ulonglong2 w0 = w0p[pq];
            ulonglong2 wi = wip[pq];
            ulonglong2 wh = whp[pq];
            ulonglong2 h, z;
            h = h0r0[q]; z = h1r0[q];
            fma2(a0[0], w0.x, h.x); fma2(a0[0], w0.y, h.y);
            fma2(aA[0], wi.x, h.x); fma2(aA[0], wi.y, h.y);
            fma2(aB[0], wh.x, z.x); fma2(aB[0], wh.y, z.y);
            h = h0r1[q]; z = h1r1[q];
            fma2(a0[1], w0.x, h.x); fma2(a0[1], w0.y, h.y);
            fma2(aA[1], wi.x, h.x); fma2(aA[1], wi.y, h.y);
            fma2(aB[1], wh.x, z.x); fma2(aB[1], wh.y, z.y);
            h = h0r2[q]; z = h1r2[q];
            fma2(a0[2], w0.x, h.x); fma2(a0[2], w0.y, h.y);
            fma2(aA[2], wi.x, h.x); fma2(aA[2], wi.y, h.y);
            fma2(aB[2], wh.x, z.x); fma2(aB[2], wh.y, z.y);
            h = h0r3[q]; z = h1r3[q];
            fma2(a0[3], w0.x, h.x); fma2(a0[3], w0.y, h.y);
            fma2(aA[3], wi.x, h.x); fma2(aA[3], wi.y, h.y);
            fma2(aB[3], wh.x, z.x); fma2(aB[3], wh.y, z.y);
        }

        // fold this K-half's slice of the x-projection into a0 (layer-0 only)
        if (k < 1024) {
#pragma unroll
            for (int bi = 0; bi < 4; bi++) {
                const float *xr = xt + (bh * 4 + bi) * 16 + kh * 8;
                float xc = 0.f;
#pragma unroll
                for (int i4 = 0; i4 < 8; i4 += 4) {
                    float4 xv = *(const float4 *)(xr + i4);
                    xc += wx[i4 + 0] * xv.x + wx[i4 + 1] * xv.y +
                          wx[i4 + 2] * xv.z + wx[i4 + 3] * xv.w;
                }
                union { float2 f; u64 u; } p; p.f = make_float2(xc, 0.f);
                add2(a0[bi], p.u);
            }
        }

        // ---- 2-way K reduction through (now dead) h-tile smem ----
        // RACE FIX (R5 bug): red aliases h0t/h1t, which the q-loop above is
        // still READING in other warps. Must sync before overwriting.
        __syncthreads();
        {
            u64 *red = (u64 *)h0t;
            if (kh) {
                u64 *r = red + (t - 256) * 13;
                r[0] = a0[0]; r[1] = a0[1]; r[2]  = a0[2]; r[3]  = a0[3];
                r[4] = aA[0]; r[5] = aA[1]; r[6]  = aA[2]; r[7]  = aA[3];
                r[8] = aB[0]; r[9] = aB[1]; r[10] = aB[2]; r[11] = aB[3];
            }
            __syncthreads();
            if (!kh) {
                u64 *r = red + t * 13;
                add2(a0[0], r[0]);  add2(a0[1], r[1]);  add2(a0[2], r[2]);  add2(a0[3], r[3]);
                add2(aA[0], r[4]);  add2(aA[1], r[5]);  add2(aA[2], r[6]);  add2(aA[3], r[7]);
                add2(aB[0], r[8]);  add2(aB[1], r[9]);  add2(aB[2], r[10]); add2(aB[3], r[11]);
            }
        }

        if (!kh) {
            if (k < 1024) {                      // layer-0 step k
#pragma unroll
                for (int bi = 0; bi < 4; bi++) {
                    float v = hsum(a0[bi]) + b0;
                    v = (g == 2) ? tanhf(v) : sigm(v);
                    float iv = __shfl_sync(0xffffffffu, v, base);
                    float fv = __shfl_sync(0xffffffffu, v, base + 1);
                    float gv = __shfl_sync(0xffffffffu, v, base + 2);
                    float ov = __shfl_sync(0xffffffffu, v, base + 3);
                    if (g == 0) {
                        c0[bi] = fv * c0[bi] + iv * gv;
                        float hh = ov * tanhf(c0[bi]);
                        __stcg(g_h0 + (k & 1) * 32768 +
                               (bg * 16 + bh * 4 + bi) * 256 + hg * 16 + j, hh);
                    }
                }
            }
            if (k >= 1) {                        // layer-1 step k-1
#pragma unroll
                for (int bi = 0; bi < 4; bi++) {
                    float v = hsum(aA[bi]) + hsum(aB[bi]) + b1;
                    v = (g == 2) ? tanhf(v) : sigm(v);
                    float iv = __shfl_sync(0xffffffffu, v, base);
                    float fv = __shfl_sync(0xffffffffu, v, base + 1);
                    float gv = __shfl_sync(0xffffffffu, v, base + 2);
                    float ov = __shfl_sync(0xffffffffu, v, base + 3);
                    if (g == 0) {
                        c1[bi] = fv * c1[bi] + iv * gv;
                        float hh = ov * tanhf(c1[bi]);
                        __stcg(g_h1 + (k & 1) * 32768 +
                               (bg * 16 + bh * 4 + bi) * 256 + hg * 16 + j, hh);
                    }
                }
            }
        }
        __threadfence();
        gridbar();
    }

    // ---- head: CTA 0, one thread per batch. h_last = layer1 state after step 1023,
    //      which iter k=1024 wrote to parity (1024&1)=0 of g_h1. ----
    if (bid == 0 && t < 128) {
        const int b = t;
        const float *h = g_h1 + b * 256;
        float s = 0.f, s2 = 0.f;
        for (int i = 0; i < 256; i++) { float v = __ldcg(h + i); s += v; s2 += v * v; }
        float mu  = s * (1.f / 256.f);
        float var = s2 * (1.f / 256.f) - mu * mu;
        float inv = rsqrtf(var + 1e-5f);
        float l0 = lb[0], l1 = lb[1], l2 = lb[2];
        for (int i = 0; i < 256; i++) {
            float v  = __ldcg(h + i);
            float hn = (v - mu) * inv * lng[i] + lnb[i];
            l0 += hn * lw[i]; l1 += hn * lw[256 + i]; l2 += hn * lw[512 + i];
        }
        float m  = fmaxf(l0, fmaxf(l1, l2));
        float e0 = __expf(l0 - m), e1 = __expf(l1 - m), e2 = __expf(l2 - m);
        float es = e0 + e1 + e2;
        float p0 = e0 / es, p1 = e1 / es, p2 = e2 / es;

        float bm[3], bs[3];
#pragma unroll
        for (int r = 0; r < 3; r++) {
            float mm = -1e30f;
            for (int p = 0; p < 32; p++) mm = fmaxf(mm, rbud[r * 32 + p]);
            float ss = 0.f;
            for (int p = 0; p < 32; p++) ss += __expf(rbud[r * 32 + p] - mm);
            bm[r] = mm; bs[r] = ss;
        }
        float w0s = p0 / bs[0], w1s = p1 / bs[1], w2s = p2 / bs[2];
        float bb[32];
        float eqs = 0.f, dfs = 0.f;
        for (int p = 0; p < 32; p++) {
            float v = w0s * __expf(rbud[p]      - bm[0]) +
                      w1s * __expf(rbud[32 + p] - bm[1]) +
                      w2s * __expf(rbud[64 + p] - bm[2]);
            bb[p] = v;
            if (p < 24) eqs += v; else dfs += v;
        }
        bool  mask      = vix[b] >= 30.0f;
        float shortfall = 0.4f - dfs;
        float ratio     = fminf(shortfall / fmaxf(eqs, 1e-8f), 0.8f);
        bool  apply     = mask && (shortfall > 0.f) && (eqs > 1e-8f);
        float bsel[32], bsum = 0.f;
        for (int p = 0; p < 32; p++) {
            float b2 = (p < 24) ? bb[p] * (1.f - ratio) : bb[p] + shortfall * (1.f / 8.f);
            float v  = apply ? b2 : bb[p];
            bsel[p] = v; bsum += v;
        }
        float innorm = 1.f / (bsum + 1e-8f);
        for (int p = 0; p < 32; p++)
            out[b * 32 + p] = mask ? bsel[p] * innorm : bb[p];
        out[4096 + b * 3 + 0] = p0;
        out[4096 + b * 3 + 1] = p1;
        out[4096 + b * 3 + 2] = p2;
    }
}

extern "C" void kernel_launch(void *const *d_in, const int *in_sizes, int n_in,
                              void *d_out, int out_size)
{
    (void)in_sizes; (void)n_in; (void)out_size;
    static int smem_set = 0;
    const int smem = 57600 * 4;   // 230400 B
    if (!smem_set) {
        cudaFuncSetAttribute(regime_kernel,
                             cudaFuncAttributeMaxDynamicSharedMemorySize, smem);
        smem_set = 1;
    }
    regime_kernel<<<NCTA, TPB, smem>>>(
        (const float *)d_in[0],  (const float *)d_in[1],  (const float *)d_in[2],
        (const float *)d_in[3],  (const float *)d_in[4],  (const float *)d_in[5],
        (const float *)d_in[6],  (const float *)d_in[7],  (const float *)d_in[8],
        (const float *)d_in[9],  (const float *)d_in[10], (const float *)d_in[11],
        (const float *)d_in[12], (const float *)d_in[13], (const float *)d_in[14],
        (float *)d_out);
}

// round 7
// speedup vs baseline: 1.0413x; 1.0025x over previous
#include <cuda_runtime.h>

#define NCTA 128
#define TPB  256

// Persistent global state (statically zero-initialized; barrier state returns
// to a consistent value after every launch, so graph replays are fine).
__device__ float g_h0[2 * 128 * 256];
__device__ float g_h1[2 * 128 * 256];
__device__ unsigned g_cnt = 0;
__device__ unsigned g_gen = 0;

typedef unsigned long long u64;

__device__ __forceinline__ void fma2(u64 &d, u64 a, u64 b) {
    asm("fma.rn.f32x2 %0, %1, %2, %0;" : "+l"(d) : "l"(a), "l"(b));
}
__device__ __forceinline__ void add2(u64 &d, u64 a) {
    asm("add.rn.f32x2 %0, %0, %1;" : "+l"(d) : "l"(a));
}
__device__ __forceinline__ float hsum(u64 a) {
    union { u64 u; float2 f; } x; x.u = a; return x.f.x + x.f.y;
}
__device__ __forceinline__ float sigm(float x) {
    return __fdividef(1.f, 1.f + __expf(-x));
}

__device__ __forceinline__ void gridbar() {
    __syncthreads();
    if (threadIdx.x == 0) {
        unsigned g = *(volatile unsigned *)&g_gen;
        __threadfence();
        if (atomicAdd(&g_cnt, 1u) == NCTA - 1) {
            g_cnt = 0;
            __threadfence();
            atomicAdd(&g_gen, 1u);
        } else {
            while (*(volatile unsigned *)&g_gen == g) { __nanosleep(32); }
        }
    }
    __syncthreads();
}

extern __shared__ float sm[];

__global__ __launch_bounds__(TPB, 1)
void regime_kernel(const float *__restrict__ X,    const float *__restrict__ vix,
                   const float *__restrict__ Wih0, const float *__restrict__ Whh0,
                   const float *__restrict__ bih0, const float *__restrict__ bhh0,
                   const float *__restrict__ Wih1, const float *__restrict__ Whh1,
                   const float *__restrict__ bih1, const float *__restrict__ bhh1,
                   const float *__restrict__ lng,  const float *__restrict__ lnb,
                   const float *__restrict__ lw,   const float *__restrict__ lb,
                   const float *__restrict__ rbud, float *__restrict__ out)
{
    float *W0  = sm;                 // 64 rows x 256, swizzled by (row>>1)&7
    float *W1i = sm + 16384;
    float *W1h = sm + 32768;
    float *h0t = sm + 49152;         // 16 x 256
    float *h1t = sm + 53248;         // 16 x 256
    float *xt  = sm + 57344;         // 16 x 16

    const int t   = threadIdx.x;
    const int bid = blockIdx.x;
    const int hg  = bid & 15;        // hidden group (16 cols)
    const int bg  = bid >> 4;        // batch group (16 rows)
    const int rp  = t & 31;          // row-pair id: rows 2rp, 2rp+1 (of 64)
    const int oq  = (t >> 5) & 3;    // batch quad: batches oq*4..oq*4+3
    const int kh  = t >> 7;          // K-half: chunks kh*32 .. kh*32+31
    const int rot = rp & 7;

    // Row semantics: jr = 2*rp + r maps to (j = rp>>1, gate g = 2*(rp&1) + r).
    const int j  = rp >> 1;
    const int g0 = (rp & 1) * 2;          // row r=0 gate: even rp -> i(0), odd -> g(2)
    const int R0 = g0 * 256 + hg * 16 + j;
    const int R1 = (g0 + 1) * 256 + hg * 16 + j;   // even -> f(1), odd -> o(3)

    // ---- load CTA weight slices into smem, XOR-16B swizzled by (row>>1) ----
    for (int idx = t; idx < 4096; idx += TPB) {
        int jr = idx >> 6, q = idx & 63;
        int gg = ((jr >> 1) & 1) * 2 + (jr & 1);
        int rr = gg * 256 + hg * 16 + (jr >> 2);
        int ds = jr * 256 + ((q ^ ((jr >> 1) & 7)) << 2);
        *(float4 *)(W0  + ds) = __ldg((const float4 *)(Whh0 + rr * 256 + q * 4));
        *(float4 *)(W1i + ds) = __ldg((const float4 *)(Wih1 + rr * 256 + q * 4));
        *(float4 *)(W1h + ds) = __ldg((const float4 *)(Whh1 + rr * 256 + q * 4));
    }
    // per-thread input weights (this K-half's 8 of 16) for both rows + biases
    float wx0[8], wx1[8];
#pragma unroll
    for (int i = 0; i < 8; i += 4) {
        float4 v0 = __ldg((const float4 *)(Wih0 + R0 * 16 + kh * 8 + i));
        float4 v1 = __ldg((const float4 *)(Wih0 + R1 * 16 + kh * 8 + i));
        wx0[i] = v0.x; wx0[i + 1] = v0.y; wx0[i + 2] = v0.z; wx0[i + 3] = v0.w;
        wx1[i] = v1.x; wx1[i + 1] = v1.y; wx1[i + 2] = v1.z; wx1[i + 3] = v1.w;
    }
    const float b00 = bih0[R0] + bhh0[R0], b01 = bih0[R1] + bhh0[R1];
    const float b10 = bih1[R0] + bhh1[R0], b11 = bih1[R1] + bhh1[R1];

    float c0[4] = {0, 0, 0, 0}, c1[4] = {0, 0, 0, 0};   // used by kh==0, even rp

    const int q0 = kh << 5;
    const ulonglong2 *w0r0 = (const ulonglong2 *)(W0  + (2 * rp)     * 256);
    const ulonglong2 *w0r1 = (const ulonglong2 *)(W0  + (2 * rp + 1) * 256);
    const ulonglong2 *wir0 = (const ulonglong2 *)(W1i + (2 * rp)     * 256);
    const ulonglong2 *wir1 = (const ulonglong2 *)(W1i + (2 * rp + 1) * 256);
    const ulonglong2 *whr0 = (const ulonglong2 *)(W1h + (2 * rp)     * 256);
    const ulonglong2 *whr1 = (const ulonglong2 *)(W1h + (2 * rp + 1) * 256);
    const ulonglong2 *h0p0 = (const ulonglong2 *)(h0t + (oq * 4 + 0) * 256);
    const ulonglong2 *h0p1 = (const ulonglong2 *)(h0t + (oq * 4 + 1) * 256);
    const ulonglong2 *h0p2 = (const ulonglong2 *)(h0t + (oq * 4 + 2) * 256);
    const ulonglong2 *h0p3 = (const ulonglong2 *)(h0t + (oq * 4 + 3) * 256);
    const ulonglong2 *h1p0 = (const ulonglong2 *)(h1t + (oq * 4 + 0) * 256);
    const ulonglong2 *h1p1 = (const ulonglong2 *)(h1t + (oq * 4 + 1) * 256);
    const ulonglong2 *h1p2 = (const ulonglong2 *)(h1t + (oq * 4 + 2) * 256);
    const ulonglong2 *h1p3 = (const ulonglong2 *)(h1t + (oq * 4 + 3) * 256);

    // ---- main pipelined recurrence: iter k does layer0 step k + layer1 step k-1 ----
    for (int k = 0; k <= 1024; k++) {
        const int pp = (k - 1) & 1;                    // read parity
        if (k == 0) {
            for (int f4 = t; f4 < 1024; f4 += TPB)
                ((float4 *)h0t)[f4] = make_float4(0, 0, 0, 0);
        } else {
            const float4 *src = (const float4 *)(g_h0 + pp * 32768 + bg * 4096);
            for (int f4 = t; f4 < 1024; f4 += TPB)
                ((float4 *)h0t)[f4] = __ldcg(src + f4);
        }
        if (k <= 1) {
            for (int f4 = t; f4 < 1024; f4 += TPB)
                ((float4 *)h1t)[f4] = make_float4(0, 0, 0, 0);
        } else {
            const float4 *src = (const float4 *)(g_h1 + pp * 32768 + bg * 4096);
            for (int f4 = t; f4 < 1024; f4 += TPB)
                ((float4 *)h1t)[f4] = __ldcg(src + f4);
        }
        if (k < 1024 && t < 64) {
            int bl = t >> 2, i4 = t & 3;
            ((float4 *)xt)[t] =
                __ldg((const float4 *)(X + ((bg * 16 + bl) * 1024 + k) * 16 + i4 * 4));
        }
        __syncthreads();

        // acc[row r][batch b]
        u64 a0[2][4] = {{0,0,0,0},{0,0,0,0}};
        u64 aA[2][4] = {{0,0,0,0},{0,0,0,0}};
        u64 aB[2][4] = {{0,0,0,0},{0,0,0,0}};
#pragma unroll 2
        for (int cc = 0; cc < 32; cc++) {
            const int q  = q0 + cc;
            const int pq = q ^ rot;
            ulonglong2 w00 = w0r0[pq], w01 = w0r1[pq];
            ulonglong2 wi0 = wir0[pq], wi1 = wir1[pq];
            ulonglong2 wh0 = whr0[pq], wh1 = whr1[pq];
            ulonglong2 h, z;
#define BODY(B, HP, ZP)                                                   \
            h = HP[q]; z = ZP[q];                                         \
            fma2(a0[0][B], w00.x, h.x); fma2(a0[0][B], w00.y, h.y);       \
            fma2(a0[1][B], w01.x, h.x); fma2(a0[1][B], w01.y, h.y);       \
            fma2(aA[0][B], wi0.x, h.x); fma2(aA[0][B], wi0.y, h.y);       \
            fma2(aA[1][B], wi1.x, h.x); fma2(aA[1][B], wi1.y, h.y);       \
            fma2(aB[0][B], wh0.x, z.x); fma2(aB[0][B], wh0.y, z.y);       \
            fma2(aB[1][B], wh1.x, z.x); fma2(aB[1][B], wh1.y, z.y);
            BODY(0, h0p0, h1p0)
            BODY(1, h0p1, h1p1)
            BODY(2, h0p2, h1p2)
            BODY(3, h0p3, h1p3)
#undef BODY
        }

        // fold this K-half's slice of the x-projection into a0 (layer-0 only)
        if (k < 1024) {
#pragma unroll
            for (int bi = 0; bi < 4; bi++) {
                const float *xr = xt + (oq * 4 + bi) * 16 + kh * 8;
                float xc0 = 0.f, xc1 = 0.f;
#pragma unroll
                for (int i4 = 0; i4 < 8; i4++) {
                    float xv = xr[i4];
                    xc0 += wx0[i4] * xv;
                    xc1 += wx1[i4] * xv;
                }
                union { float2 f; u64 u; } p0, p1;
                p0.f = make_float2(xc0, 0.f);
                p1.f = make_float2(xc1, 0.f);
                add2(a0[0][bi], p0.u);
                add2(a0[1][bi], p1.u);
            }
        }

        // ---- 2-way K reduction through (now dead) h-tile smem ----
        // red aliases h0t/h1t which the q-loop reads: sync before overwriting.
        __syncthreads();
        {
            ulonglong2 *red = (ulonglong2 *)h0t;     // 128 threads * 24 u64 = 24KB
            if (kh) {
                ulonglong2 *r = red + (t - 128) * 12;
                r[0]  = make_ulonglong2(a0[0][0], a0[0][1]);
                r[1]  = make_ulonglong2(a0[0][2], a0[0][3]);
                r[2]  = make_ulonglong2(a0[1][0], a0[1][1]);
                r[3]  = make_ulonglong2(a0[1][2], a0[1][3]);
                r[4]  = make_ulonglong2(aA[0][0], aA[0][1]);
                r[5]  = make_ulonglong2(aA[0][2], aA[0][3]);
                r[6]  = make_ulonglong2(aA[1][0], aA[1][1]);
                r[7]  = make_ulonglong2(aA[1][2], aA[1][3]);
                r[8]  = make_ulonglong2(aB[0][0], aB[0][1]);
                r[9]  = make_ulonglong2(aB[0][2], aB[0][3]);
                r[10] = make_ulonglong2(aB[1][0], aB[1][1]);
                r[11] = make_ulonglong2(aB[1][2], aB[1][3]);
            }
            __syncthreads();
            if (!kh) {
                ulonglong2 *r = red + t * 12;
                ulonglong2 v;
                v = r[0];  add2(a0[0][0], v.x); add2(a0[0][1], v.y);
                v = r[1];  add2(a0[0][2], v.x); add2(a0[0][3], v.y);
                v = r[2];  add2(a0[1][0], v.x); add2(a0[1][1], v.y);
                v = r[3];  add2(a0[1][2], v.x); add2(a0[1][3], v.y);
                v = r[4];  add2(aA[0][0], v.x); add2(aA[0][1], v.y);
                v = r[5];  add2(aA[0][2], v.x); add2(aA[0][3], v.y);
                v = r[6];  add2(aA[1][0], v.x); add2(aA[1][1], v.y);
                v = r[7];  add2(aA[1][2], v.x); add2(aA[1][3], v.y);
                v = r[8];  add2(aB[0][0], v.x); add2(aB[0][1], v.y);
                v = r[9];  add2(aB[0][2], v.x); add2(aB[0][3], v.y);
                v = r[10]; add2(aB[1][0], v.x); add2(aB[1][1], v.y);
                v = r[11]; add2(aB[1][2], v.x); add2(aB[1][3], v.y);
            }
        }

        // ---- gates: kh==0 threads (warps 0-3, full warps -> shfl ok) ----
        if (!kh) {
            const bool oddr = (rp & 1) != 0;
            if (k < 1024) {                      // layer-0 step k
#pragma unroll
                for (int bi = 0; bi < 4; bi++) {
                    float v0 = hsum(a0[0][bi]) + b00;   // gate i (even) / g (odd)
                    float v1 = hsum(a0[1][bi]) + b01;   // gate f (even) / o (odd)
                    float e0 = oddr ? tanhf(v0) : sigm(v0);
                    float e1 = sigm(v1);
                    float p0 = __shfl_xor_sync(0xffffffffu, e0, 1);
                    float p1 = __shfl_xor_sync(0xffffffffu, e1, 1);
                    if (!oddr) {
                        c0[bi] = e1 * c0[bi] + e0 * p0;
                        float hh = p1 * tanhf(c0[bi]);
                        __stcg(g_h0 + (k & 1) * 32768 +
                               (bg * 16 + oq * 4 + bi) * 256 + hg * 16 + j, hh);
                    }
                }
            }
            if (k >= 1) {                        // layer-1 step k-1
#pragma unroll
                for (int bi = 0; bi < 4; bi++) {
                    float v0 = hsum(aA[0][bi]) + hsum(aB[0][bi]) + b10;
                    float v1 = hsum(aA[1][bi]) + hsum(aB[1][bi]) + b11;
                    float e0 = oddr ? tanhf(v0) : sigm(v0);
                    float e1 = sigm(v1);
                    float p0 = __shfl_xor_sync(0xffffffffu, e0, 1);
                    float p1 = __shfl_xor_sync(0xffffffffu, e1, 1);
                    if (!oddr) {
                        c1[bi] = e1 * c1[bi] + e0 * p0;
                        float hh = p1 * tanhf(c1[bi]);
                        __stcg(g_h1 + (k & 1) * 32768 +
                               (bg * 16 + oq * 4 + bi) * 256 + hg * 16 + j, hh);
                    }
                }
            }
        }
        __threadfence();
        gridbar();
    }

    // ---- head: CTA 0, one thread per batch. h_last = layer1 state after step 1023,
    //      written at parity (1024&1)=0 of g_h1. ----
    if (bid == 0 && t < 128) {
        const int b = t;
        const float *h = g_h1 + b * 256;
        float s = 0.f, s2 = 0.f;
        for (int i = 0; i < 256; i++) { float v = __ldcg(h + i); s += v; s2 += v * v; }
        float mu  = s * (1.f / 256.f);
        float var = s2 * (1.f / 256.f) - mu * mu;
        float inv = rsqrtf(var + 1e-5f);
        float l0 = lb[0], l1 = lb[1], l2 = lb[2];
        for (int i = 0; i < 256; i++) {
            float v  = __ldcg(h + i);
            float hn = (v - mu) * inv * lng[i] + lnb[i];
            l0 += hn * lw[i]; l1 += hn * lw[256 + i]; l2 += hn * lw[512 + i];
        }
        float m  = fmaxf(l0, fmaxf(l1, l2));
        float e0 = __expf(l0 - m), e1 = __expf(l1 - m), e2 = __expf(l2 - m);
        float es = e0 + e1 + e2;
        float p0 = e0 / es, p1 = e1 / es, p2 = e2 / es;

        float bm[3], bs[3];
#pragma unroll
        for (int r = 0; r < 3; r++) {
            float mm = -1e30f;
            for (int p = 0; p < 32; p++) mm = fmaxf(mm, rbud[r * 32 + p]);
            float ss = 0.f;
            for (int p = 0; p < 32; p++) ss += __expf(rbud[r * 32 + p] - mm);
            bm[r] = mm; bs[r] = ss;
        }
        float w0s = p0 / bs[0], w1s = p1 / bs[1], w2s = p2 / bs[2];
        float bb[32];
        float eqs = 0.f, dfs = 0.f;
        for (int p = 0; p < 32; p++) {
            float v = w0s * __expf(rbud[p]      - bm[0]) +
                      w1s * __expf(rbud[32 + p] - bm[1]) +
                      w2s * __expf(rbud[64 + p] - bm[2]);
            bb[p] = v;
            if (p < 24) eqs += v; else dfs += v;
        }
        bool  mask      = vix[b] >= 30.0f;
        float shortfall = 0.4f - dfs;
        float ratio     = fminf(shortfall / fmaxf(eqs, 1e-8f), 0.8f);
        bool  apply     = mask && (shortfall > 0.f) && (eqs > 1e-8f);
        float bsel[32], bsum = 0.f;
        for (int p = 0; p < 32; p++) {
            float b2 = (p < 24) ? bb[p] * (1.f - ratio) : bb[p] + shortfall * (1.f / 8.f);
            float v  = apply ? b2 : bb[p];
            bsel[p] = v; bsum += v;
        }
        float innorm = 1.f / (bsum + 1e-8f);
        for (int p = 0; p < 32; p++)
            out[b * 32 + p] = mask ? bsel[p] * innorm : bb[p];
        out[4096 + b * 3 + 0] = p0;
        out[4096 + b * 3 + 1] = p1;
        out[4096 + b * 3 + 2] = p2;
    }
}

extern "C" void kernel_launch(void *const *d_in, const int *in_sizes, int n_in,
                              void *d_out, int out_size)
{
    (void)in_sizes; (void)n_in; (void)out_size;
    static int smem_set = 0;
    const int smem = 57600 * 4;   // 230400 B
    if (!smem_set) {
        cudaFuncSetAttribute(regime_kernel,
                             cudaFuncAttributeMaxDynamicSharedMemorySize, smem);
        smem_set = 1;
    }
    regime_kernel<<<NCTA, TPB, smem>>>(
        (const float *)d_in[0],  (const float *)d_in[1],  (const float *)d_in[2],
        (const float *)d_in[3],  (const float *)d_in[4],  (const float *)d_in[5],
        (const float *)d_in[6],  (const float *)d_in[7],  (const float *)d_in[8],
        (const float *)d_in[9],  (const float *)d_in[10], (const float *)d_in[11],
        (const float *)d_in[12], (const float *)d_in[13], (const float *)d_in[14],
        (float *)d_out);
}